// round 1
// baseline (speedup 1.0000x reference)
#include <cuda_runtime.h>
#include <math.h>

// Problem constants (fixed by the dataset instance)
#define BATCH   8
#define NP      4096          // N == M == 4096
#define FDIM    512
#define H1DIM   256
#define H2DIM   128
#define DDIM    6

#define FSCORE_W 0.1f
#define TASK_W   1.0f
#define DOMAIN_W 0.1f
// c = 2*sigma^2 = 2e-4; -d/c = -d * 5000
#define INV_C    5000.0f

// Chamfer tiling
#define TPB     128           // threads per block
#define PPT     4             // query points per thread
#define QTILE   (TPB*PPT)     // 512 query points per block
#define KSPLIT  8             // key-dimension split (atomics combine)
#define KCHUNK  (NP/KSPLIT)   // 512 keys per block
#define KTILE   128           // shared tile of keys

// Scratch (device globals: no allocation allowed)
__device__ float g_min_a[BATCH * NP];
__device__ float g_min_b[BATCH * NP];
__device__ float g_sums[BATCH * 4];   // sumA, sumEA, sumB, sumEB per batch
__device__ float g_dom[BATCH];

__device__ __forceinline__ void atomicMinFloat(float* addr, float val) {
    // Correct float-min atomic via signed/unsigned split (addr init to +INF).
    if (val >= 0.0f) {
        atomicMin((int*)addr, __float_as_int(val));
    } else {
        atomicMax((unsigned int*)addr, __float_as_uint(val));
    }
}

__global__ void init_kernel() {
    int i = blockIdx.x * blockDim.x + threadIdx.x;
    float inf = __int_as_float(0x7f800000);
    if (i < BATCH * NP) {
        g_min_a[i] = inf;
        g_min_b[i] = inf;
    }
}

// For each query q in its tile: d_min over assigned key chunk of |q-k|^2,
// using d = |q|^2 + (|k|^2 - 2 q.k). atomicMin into out[b*NP + q].
__global__ __launch_bounds__(TPB) void chamfer_kernel(
    const float* __restrict__ Q, const float* __restrict__ K, float* __restrict__ out)
{
    const int b  = blockIdx.z;
    const int q0 = blockIdx.x * QTILE;
    const int k0 = blockIdx.y * KCHUNK;
    const int tid = threadIdx.x;

    __shared__ float4 sk[KTILE];

    const float* Qb = Q + (size_t)b * NP * 3;
    const float* Kb = K + (size_t)b * NP * 3;

    float qx[PPT], qy[PPT], qz[PPT], emin[PPT];
    #pragma unroll
    for (int p = 0; p < PPT; p++) {
        int q = q0 + p * TPB + tid;
        qx[p] = Qb[q * 3 + 0];
        qy[p] = Qb[q * 3 + 1];
        qz[p] = Qb[q * 3 + 2];
        emin[p] = __int_as_float(0x7f800000);
    }

    for (int kt = 0; kt < KCHUNK; kt += KTILE) {
        __syncthreads();
        {
            int k = k0 + kt + tid;   // TPB == KTILE: every thread loads one key
            float kx = Kb[k * 3 + 0];
            float ky = Kb[k * 3 + 1];
            float kz = Kb[k * 3 + 2];
            sk[tid] = make_float4(-2.0f * kx, -2.0f * ky, -2.0f * kz,
                                  kx * kx + ky * ky + kz * kz);
        }
        __syncthreads();

        #pragma unroll 4
        for (int j = 0; j < KTILE; j++) {
            float4 s = sk[j];            // broadcast LDS.128
            #pragma unroll
            for (int p = 0; p < PPT; p++) {
                float e = fmaf(qx[p], s.x, s.w);
                e = fmaf(qy[p], s.y, e);
                e = fmaf(qz[p], s.z, e);
                emin[p] = fminf(emin[p], e);
            }
        }
    }

    #pragma unroll
    for (int p = 0; p < PPT; p++) {
        int q = q0 + p * TPB + tid;
        float q2 = qx[p] * qx[p] + qy[p] * qy[p] + qz[p] * qz[p];
        atomicMinFloat(&out[b * NP + q], emin[p] + q2);
    }
}

// Per-batch sums of min distances and soft (exp) terms, both directions.
__global__ void reduce_kernel() {
    const int b = blockIdx.x;
    const int tid = threadIdx.x;
    float sA = 0.f, sEA = 0.f, sB = 0.f, sEB = 0.f;
    for (int n = tid; n < NP; n += blockDim.x) {
        float da = g_min_a[b * NP + n];
        float db = g_min_b[b * NP + n];
        sA += da;  sEA += expf(-da * INV_C);
        sB += db;  sEB += expf(-db * INV_C);
    }
    __shared__ float red[256 * 4];
    red[tid * 4 + 0] = sA;
    red[tid * 4 + 1] = sEA;
    red[tid * 4 + 2] = sB;
    red[tid * 4 + 3] = sEB;
    __syncthreads();
    for (int s = 128; s > 0; s >>= 1) {
        if (tid < s) {
            red[tid * 4 + 0] += red[(tid + s) * 4 + 0];
            red[tid * 4 + 1] += red[(tid + s) * 4 + 1];
            red[tid * 4 + 2] += red[(tid + s) * 4 + 2];
            red[tid * 4 + 3] += red[(tid + s) * 4 + 3];
        }
        __syncthreads();
    }
    if (tid == 0) {
        g_sums[b * 4 + 0] = red[0];
        g_sums[b * 4 + 1] = red[1];
        g_sums[b * 4 + 2] = red[2];
        g_sums[b * 4 + 3] = red[3];
    }
}

// Domain classifier: 512 -> relu 256 -> relu 128 -> 6 logits -> NLL per batch.
__global__ __launch_bounds__(H1DIM) void domain_kernel(
    const float* __restrict__ X,
    const float* __restrict__ W1, const float* __restrict__ b1,
    const float* __restrict__ W2, const float* __restrict__ b2,
    const float* __restrict__ W3, const float* __restrict__ b3,
    const int* __restrict__ labels)
{
    const int b = blockIdx.x;
    const int tid = threadIdx.x;
    __shared__ float xs[FDIM];
    __shared__ float h1[H1DIM];
    __shared__ float h2[H2DIM];
    __shared__ float lg[DDIM];

    for (int i = tid; i < FDIM; i += H1DIM) xs[i] = X[b * FDIM + i];
    __syncthreads();

    {
        float a = b1[tid];
        for (int f = 0; f < FDIM; f++)
            a = fmaf(xs[f], W1[f * H1DIM + tid], a);
        h1[tid] = fmaxf(a, 0.0f);
    }
    __syncthreads();
    if (tid < H2DIM) {
        float a = b2[tid];
        for (int k = 0; k < H1DIM; k++)
            a = fmaf(h1[k], W2[k * H2DIM + tid], a);
        h2[tid] = fmaxf(a, 0.0f);
    }
    __syncthreads();
    if (tid < DDIM) {
        float a = b3[tid];
        for (int k = 0; k < H2DIM; k++)
            a = fmaf(h2[k], W3[k * DDIM + tid], a);
        lg[tid] = a;
    }
    __syncthreads();
    if (tid == 0) {
        float mx = lg[0];
        for (int d = 1; d < DDIM; d++) mx = fmaxf(mx, lg[d]);
        float se = 0.f;
        for (int d = 0; d < DDIM; d++) se += expf(lg[d] - mx);
        float lse = mx + logf(se);
        g_dom[b] = lse - lg[labels[b]];
    }
}

__global__ void combine_kernel(const float* __restrict__ dsw, float* __restrict__ out) {
    float totA = 0.f, totEA = 0.f, totB = 0.f, totEB = 0.f;
    float dw = 0.f, dom = 0.f;
    const float invN = 1.0f / (float)NP;
    for (int b = 0; b < BATCH; b++) {
        float sA  = g_sums[b * 4 + 0];
        float sEA = g_sums[b * 4 + 1];
        float sB  = g_sums[b * 4 + 2];
        float sEB = g_sums[b * 4 + 3];
        totA += sA; totEA += sEA; totB += sB; totEB += sEB;
        float ch_i = sA * invN + sB * invN;
        float p_i  = sEA * invN;
        float r_i  = sEB * invN;
        float f_i  = 2.0f * p_i * r_i / (p_i + r_i + 1e-8f);
        float loss_i = ch_i + FSCORE_W * (1.0f - f_i);
        dw  += dsw[b] * loss_i;
        dom += g_dom[b];
    }
    dw  /= (float)BATCH;
    dom /= (float)BATCH;
    const float invBN = 1.0f / (float)(BATCH * NP);
    float chamfer = totA * invBN + totB * invBN;
    float prec = totEA * invBN;
    float rec  = totEB * invBN;
    float fscore = 2.0f * prec * rec / (prec + rec + 1e-8f);
    float task = chamfer + FSCORE_W * (1.0f - fscore);
    out[0] = TASK_W * task + DOMAIN_W * dom + dw;
}

extern "C" void kernel_launch(void* const* d_in, const int* in_sizes, int n_in,
                              void* d_out, int out_size)
{
    const float* pred_pc  = (const float*)d_in[0];
    const float* target_pc= (const float*)d_in[1];
    const float* dfeat    = (const float*)d_in[2];
    const float* dsw      = (const float*)d_in[3];
    const float* W1 = (const float*)d_in[4];
    const float* b1 = (const float*)d_in[5];
    const float* W2 = (const float*)d_in[6];
    const float* b2 = (const float*)d_in[7];
    const float* W3 = (const float*)d_in[8];
    const float* b3 = (const float*)d_in[9];
    const int*   labels = (const int*)d_in[10];
    float* out = (float*)d_out;

    float* p_min_a = nullptr;
    float* p_min_b = nullptr;
    cudaGetSymbolAddress((void**)&p_min_a, g_min_a);
    cudaGetSymbolAddress((void**)&p_min_b, g_min_b);

    init_kernel<<<(BATCH * NP + 255) / 256, 256>>>();

    dim3 grid(NP / QTILE, KSPLIT, BATCH);   // (8, 8, 8) = 512 blocks
    chamfer_kernel<<<grid, TPB>>>(pred_pc,  target_pc, p_min_a);
    chamfer_kernel<<<grid, TPB>>>(target_pc, pred_pc,  p_min_b);

    reduce_kernel<<<BATCH, 256>>>();
    domain_kernel<<<BATCH, H1DIM>>>(dfeat, W1, b1, W2, b2, W3, b3, labels);
    combine_kernel<<<1, 1>>>(dsw, out);
}

// round 2
// speedup vs baseline: 1.2859x; 1.2859x over previous
#include <cuda_runtime.h>
#include <math.h>

// Problem constants (fixed by the dataset instance)
#define BATCH   8
#define NP      4096
#define FDIM    512
#define H1DIM   256
#define H2DIM   128
#define DDIM    6

#define FSCORE_W 0.1f
#define TASK_W   1.0f
#define DOMAIN_W 0.1f
#define INV_C    5000.0f       // 1/(2*sigma^2)

// Chamfer tiling
#define TPB     128
#define PPT     4
#define QTILE   (TPB*PPT)      // 512 queries per block
#define KSPLIT  16
#define KCHUNK  (NP/KSPLIT)    // 256 keys per block
#define KTILE   128            // keys per shared tile (2 tiles per block)

// Scratch (device globals: no allocation allowed)
__device__ float g_min_a[BATCH * NP];
__device__ float g_min_b[BATCH * NP];
__device__ float g_sums[BATCH * 4];   // sumA, sumEA, sumB, sumEB per batch
__device__ float g_dom[BATCH];

// ---------------- f32x2 helpers (sm_100+ packed fp32) ----------------
__device__ __forceinline__ unsigned long long pack2(float lo, float hi) {
    unsigned long long r;
    asm("mov.b64 %0, {%1, %2};" : "=l"(r) : "f"(lo), "f"(hi));
    return r;
}
__device__ __forceinline__ unsigned long long fma2(unsigned long long a,
                                                   unsigned long long b,
                                                   unsigned long long c) {
    unsigned long long r;
    asm("fma.rn.f32x2 %0, %1, %2, %3;" : "=l"(r) : "l"(a), "l"(b), "l"(c));
    return r;
}
__device__ __forceinline__ float2 unpack2(unsigned long long v) {
    float2 f;
    asm("mov.b64 {%0, %1}, %2;" : "=f"(f.x), "=f"(f.y) : "l"(v));
    return f;
}

__device__ __forceinline__ void atomicMinFloat(float* addr, float val) {
    if (val >= 0.0f) {
        atomicMin((int*)addr, __float_as_int(val));
    } else {
        atomicMax((unsigned int*)addr, __float_as_uint(val));
    }
}

__global__ void init_kernel() {
    int i = blockIdx.x * blockDim.x + threadIdx.x;
    float inf = __int_as_float(0x7f800000);
    if (i < BATCH * NP) {
        g_min_a[i] = inf;
        g_min_b[i] = inf;
    }
    if (i < BATCH * 4) g_sums[i] = 0.0f;
}

// For each query q: min over assigned key chunk of |q-k|^2, via
// d = |q|^2 + (|k|^2 - 2 q.k). Keys are processed in f32x2 PAIRS so the
// 3-FMA chain runs on the packed FFMA2 pipe (2 distances per chain).
__global__ __launch_bounds__(TPB) void chamfer_kernel(
    const float* __restrict__ Q, const float* __restrict__ K, float* __restrict__ out)
{
    const int b  = blockIdx.z;
    const int q0 = blockIdx.x * QTILE;
    const int k0 = blockIdx.y * KCHUNK;
    const int tid = threadIdx.x;

    // skA[j].x = {-2x_{2j}, -2x_{2j+1}}   skA[j].y = {-2y...}
    // skB[j].x = {-2z...}                 skB[j].y = {|k|^2 pair}
    __shared__ ulonglong2 skA[KTILE / 2];
    __shared__ ulonglong2 skB[KTILE / 2];

    const float* Qb = Q + (size_t)b * NP * 3;
    const float* Kb = K + (size_t)b * NP * 3;

    unsigned long long qxd[PPT], qyd[PPT], qzd[PPT];
    float q2[PPT], emin[PPT];
    #pragma unroll
    for (int p = 0; p < PPT; p++) {
        int q = q0 + p * TPB + tid;
        float qx = Qb[q * 3 + 0];
        float qy = Qb[q * 3 + 1];
        float qz = Qb[q * 3 + 2];
        qxd[p] = pack2(qx, qx);
        qyd[p] = pack2(qy, qy);
        qzd[p] = pack2(qz, qz);
        q2[p]  = qx * qx + qy * qy + qz * qz;
        emin[p] = __int_as_float(0x7f800000);
    }

    for (int kt = 0; kt < KCHUNK; kt += KTILE) {
        __syncthreads();
        if (tid < KTILE / 2) {
            int k = k0 + kt + 2 * tid;
            float kx0 = Kb[k * 3 + 0], ky0 = Kb[k * 3 + 1], kz0 = Kb[k * 3 + 2];
            float kx1 = Kb[k * 3 + 3], ky1 = Kb[k * 3 + 4], kz1 = Kb[k * 3 + 5];
            ulonglong2 A, B;
            A.x = pack2(-2.0f * kx0, -2.0f * kx1);
            A.y = pack2(-2.0f * ky0, -2.0f * ky1);
            B.x = pack2(-2.0f * kz0, -2.0f * kz1);
            B.y = pack2(kx0 * kx0 + ky0 * ky0 + kz0 * kz0,
                        kx1 * kx1 + ky1 * ky1 + kz1 * kz1);
            skA[tid] = A;
            skB[tid] = B;
        }
        __syncthreads();

        #pragma unroll 4
        for (int j = 0; j < KTILE / 2; j++) {
            ulonglong2 A = skA[j];   // LDS.128
            ulonglong2 B = skB[j];   // LDS.128
            #pragma unroll
            for (int p = 0; p < PPT; p++) {
                unsigned long long e = fma2(qxd[p], A.x, B.y);
                e = fma2(qyd[p], A.y, e);
                e = fma2(qzd[p], B.x, e);
                float2 ef = unpack2(e);
                emin[p] = fminf(emin[p], fminf(ef.x, ef.y));
            }
        }
    }

    #pragma unroll
    for (int p = 0; p < PPT; p++) {
        int q = q0 + p * TPB + tid;
        atomicMinFloat(&out[b * NP + q], emin[p] + q2[p]);
    }
}

// Per-batch sums of min distances and soft (exp) terms, both directions.
// Grid (4, BATCH): 4 blocks per batch, float4 loads, atomicAdd combine.
__global__ __launch_bounds__(256) void reduce_kernel() {
    const int b = blockIdx.y;
    const int tid = threadIdx.x;
    const int base = b * NP + blockIdx.x * 1024 + tid * 4;

    const float4* pa = (const float4*)&g_min_a[0];
    const float4* pb = (const float4*)&g_min_b[0];
    float4 da = pa[base >> 2];
    float4 db = pb[base >> 2];

    float sA  = da.x + da.y + da.z + da.w;
    float sEA = __expf(-da.x * INV_C) + __expf(-da.y * INV_C)
              + __expf(-da.z * INV_C) + __expf(-da.w * INV_C);
    float sB  = db.x + db.y + db.z + db.w;
    float sEB = __expf(-db.x * INV_C) + __expf(-db.y * INV_C)
              + __expf(-db.z * INV_C) + __expf(-db.w * INV_C);

    #pragma unroll
    for (int s = 16; s > 0; s >>= 1) {
        sA  += __shfl_xor_sync(0xffffffffu, sA,  s);
        sEA += __shfl_xor_sync(0xffffffffu, sEA, s);
        sB  += __shfl_xor_sync(0xffffffffu, sB,  s);
        sEB += __shfl_xor_sync(0xffffffffu, sEB, s);
    }

    __shared__ float red[8][4];
    int w = tid >> 5;
    if ((tid & 31) == 0) {
        red[w][0] = sA; red[w][1] = sEA; red[w][2] = sB; red[w][3] = sEB;
    }
    __syncthreads();
    if (tid < 4) {
        float acc = 0.f;
        #pragma unroll
        for (int ww = 0; ww < 8; ww++) acc += red[ww][tid];
        atomicAdd(&g_sums[b * 4 + tid], acc);
    }
}

// Domain classifier: 512 -> relu 256 -> relu 128 -> 6 logits -> NLL per batch.
__global__ __launch_bounds__(H1DIM) void domain_kernel(
    const float* __restrict__ X,
    const float* __restrict__ W1, const float* __restrict__ b1,
    const float* __restrict__ W2, const float* __restrict__ b2,
    const float* __restrict__ W3, const float* __restrict__ b3,
    const int* __restrict__ labels)
{
    const int b = blockIdx.x;
    const int tid = threadIdx.x;
    __shared__ float xs[FDIM];
    __shared__ float h1[H1DIM];
    __shared__ float h2[H2DIM];
    __shared__ float lg[DDIM];

    for (int i = tid; i < FDIM; i += H1DIM) xs[i] = X[b * FDIM + i];
    __syncthreads();

    {
        float a = b1[tid];
        for (int f = 0; f < FDIM; f++)
            a = fmaf(xs[f], W1[f * H1DIM + tid], a);
        h1[tid] = fmaxf(a, 0.0f);
    }
    __syncthreads();
    if (tid < H2DIM) {
        float a = b2[tid];
        for (int k = 0; k < H1DIM; k++)
            a = fmaf(h1[k], W2[k * H2DIM + tid], a);
        h2[tid] = fmaxf(a, 0.0f);
    }
    __syncthreads();
    if (tid < DDIM) {
        float a = b3[tid];
        for (int k = 0; k < H2DIM; k++)
            a = fmaf(h2[k], W3[k * DDIM + tid], a);
        lg[tid] = a;
    }
    __syncthreads();
    if (tid == 0) {
        float mx = lg[0];
        for (int d = 1; d < DDIM; d++) mx = fmaxf(mx, lg[d]);
        float se = 0.f;
        for (int d = 0; d < DDIM; d++) se += expf(lg[d] - mx);
        float lse = mx + logf(se);
        g_dom[b] = lse - lg[labels[b]];
    }
}

__global__ void combine_kernel(const float* __restrict__ dsw, float* __restrict__ out) {
    float totA = 0.f, totEA = 0.f, totB = 0.f, totEB = 0.f;
    float dw = 0.f, dom = 0.f;
    const float invN = 1.0f / (float)NP;
    for (int b = 0; b < BATCH; b++) {
        float sA  = g_sums[b * 4 + 0];
        float sEA = g_sums[b * 4 + 1];
        float sB  = g_sums[b * 4 + 2];
        float sEB = g_sums[b * 4 + 3];
        totA += sA; totEA += sEA; totB += sB; totEB += sEB;
        float ch_i = sA * invN + sB * invN;
        float p_i  = sEA * invN;
        float r_i  = sEB * invN;
        float f_i  = 2.0f * p_i * r_i / (p_i + r_i + 1e-8f);
        float loss_i = ch_i + FSCORE_W * (1.0f - f_i);
        dw  += dsw[b] * loss_i;
        dom += g_dom[b];
    }
    dw  /= (float)BATCH;
    dom /= (float)BATCH;
    const float invBN = 1.0f / (float)(BATCH * NP);
    float chamfer = totA * invBN + totB * invBN;
    float prec = totEA * invBN;
    float rec  = totEB * invBN;
    float fscore = 2.0f * prec * rec / (prec + rec + 1e-8f);
    float task = chamfer + FSCORE_W * (1.0f - fscore);
    out[0] = TASK_W * task + DOMAIN_W * dom + dw;
}

extern "C" void kernel_launch(void* const* d_in, const int* in_sizes, int n_in,
                              void* d_out, int out_size)
{
    const float* pred_pc   = (const float*)d_in[0];
    const float* target_pc = (const float*)d_in[1];
    const float* dfeat     = (const float*)d_in[2];
    const float* dsw       = (const float*)d_in[3];
    const float* W1 = (const float*)d_in[4];
    const float* b1 = (const float*)d_in[5];
    const float* W2 = (const float*)d_in[6];
    const float* b2 = (const float*)d_in[7];
    const float* W3 = (const float*)d_in[8];
    const float* b3 = (const float*)d_in[9];
    const int*   labels = (const int*)d_in[10];
    float* out = (float*)d_out;

    float* p_min_a = nullptr;
    float* p_min_b = nullptr;
    cudaGetSymbolAddress((void**)&p_min_a, g_min_a);
    cudaGetSymbolAddress((void**)&p_min_b, g_min_b);

    init_kernel<<<(BATCH * NP + 255) / 256, 256>>>();

    dim3 grid(NP / QTILE, KSPLIT, BATCH);   // (8, 16, 8) = 1024 blocks
    chamfer_kernel<<<grid, TPB>>>(pred_pc,   target_pc, p_min_a);
    chamfer_kernel<<<grid, TPB>>>(target_pc, pred_pc,   p_min_b);

    dim3 rgrid(4, BATCH);
    reduce_kernel<<<rgrid, 256>>>();
    domain_kernel<<<BATCH, H1DIM>>>(dfeat, W1, b1, W2, b2, W3, b3, labels);
    combine_kernel<<<1, 1>>>(dsw, out);
}